// round 4
// baseline (speedup 1.0000x reference)
#include <cuda_runtime.h>

#define NODES   4096
#define PAIRS   (NODES / 2)
#define THREADS 1024
#define R       4            // rows per block
#define ITERS   (NODES / THREADS)   // 4

// Compressed per-output-node map (SoA):
//   g_src[n] = src0 | (src1 << 12)
//   g_cs[n]  = {a, b}   with  out[row][n] = a*row[src0] + b*row[src1]
__device__ int    g_src[NODES];
__device__ float2 g_cs[NODES];

__global__ void setup_kernel(const float* __restrict__ angles,
                             const int* __restrict__ pairs,
                             const int* __restrict__ outp_pairs) {
    int p = blockIdx.x * blockDim.x + threadIdx.x;
    if (p < PAIRS) {
        float s, c;
        sincosf(angles[p], &s, &c);
        int a0 = pairs[2 * p];
        int a1 = pairs[2 * p + 1];
        int o0 = outp_pairs[2 * p];
        int o1 = outp_pairs[2 * p + 1];
        // yi = c*x[a0] - s*x[a1] -> out[o0]
        // yj = c*x[a1] + s*x[a0] -> out[o1]
        g_src[o0] = a0 | (a1 << 12);
        g_cs[o0]  = make_float2(c, -s);
        g_src[o1] = a1 | (a0 << 12);
        g_cs[o1]  = make_float2(c, s);
    }
}

// Dynamic smem: float4 s_tile[NODES]; s_tile[n] = rows r0..r3 at node n (64 KB).
extern __shared__ float4 s_tile[];

__global__ void __launch_bounds__(THREADS, 2)
rot_kernel(const float* __restrict__ inp, float* __restrict__ outp) {
    const int tid = threadIdx.x;
    const size_t base = (size_t)blockIdx.x * R * NODES;

    const float* r0 = inp + base;
    const float* r1 = r0 + NODES;
    const float* r2 = r1 + NODES;
    const float* r3 = r2 + NODES;

    // Prefetch map entries — independent of staged data, overlaps staging latency.
    int    msrc[ITERS];
    float2 mcs[ITERS];
#pragma unroll
    for (int i = 0; i < ITERS; i++) {
        int n = tid + i * THREADS;
        msrc[i] = g_src[n];
        mcs[i]  = g_cs[n];
    }

    // Stage: transpose R rows into [node][row] float4 records.
    // 4 coalesced LDG.32 + 1 sequential STS.128 (conflict-free) per node.
#pragma unroll
    for (int i = 0; i < ITERS; i++) {
        int n = tid + i * THREADS;
        float4 v;
        v.x = r0[n];
        v.y = r1[n];
        v.z = r2[n];
        v.w = r3[n];
        s_tile[n] = v;
    }
    __syncthreads();

    float* o0 = outp + base;
    float* o1 = o0 + NODES;
    float* o2 = o1 + NODES;
    float* o3 = o2 + NODES;

    // Gather: two random LDS.128 produce all R rows of output node n.
#pragma unroll
    for (int i = 0; i < ITERS; i++) {
        int n  = tid + i * THREADS;
        int s0 = msrc[i] & 0xFFF;
        int s1 = msrc[i] >> 12;
        float a = mcs[i].x;
        float b = mcs[i].y;
        float4 x = s_tile[s0];
        float4 y = s_tile[s1];
        o0[n] = a * x.x + b * y.x;
        o1[n] = a * x.y + b * y.y;
        o2[n] = a * x.z + b * y.z;
        o3[n] = a * x.w + b * y.w;
    }
}

extern "C" void kernel_launch(void* const* d_in, const int* in_sizes, int n_in,
                              void* d_out, int out_size) {
    const float* inp        = (const float*)d_in[0];
    const float* angles     = (const float*)d_in[1];
    const int*   pairs      = (const int*)d_in[2];
    const int*   outp_pairs = (const int*)d_in[3];
    float*       outp       = (float*)d_out;

    int rows = in_sizes[0] / NODES;           // 8192
    int smem = NODES * sizeof(float4);        // 64 KB

    static bool attr_set = false;
    if (!attr_set) {
        cudaFuncSetAttribute(rot_kernel,
                             cudaFuncAttributeMaxDynamicSharedMemorySize, smem);
        attr_set = true;
    }

    // Spread the sincosf latency across many SMs.
    setup_kernel<<<32, 64>>>(angles, pairs, outp_pairs);
    rot_kernel<<<rows / R, THREADS, smem>>>(inp, outp);
}

// round 5
// speedup vs baseline: 1.1740x; 1.1740x over previous
#include <cuda_runtime.h>

#define NODES   4096
#define PAIRS   (NODES / 2)
#define THREADS 512
#define R       4                   // rows per block
#define ITERS   (NODES / THREADS)   // 8

// Compressed per-output-node map (SoA):
//   g_src[n] = src0 | (src1 << 12)
//   g_cs[n]  = {a, b}   with  out[row][n] = a*row[src0] + b*row[src1]
__device__ int    g_src[NODES];
__device__ float2 g_cs[NODES];

__global__ void setup_kernel(const float* __restrict__ angles,
                             const int* __restrict__ pairs,
                             const int* __restrict__ outp_pairs) {
    // Let the dependent rot_kernel launch immediately; it only consumes the
    // map after cudaGridDependencySynchronize(), which waits for this grid's
    // completion (with memory flush).
    cudaTriggerProgrammaticLaunchCompletion();

    int p = blockIdx.x * blockDim.x + threadIdx.x;
    if (p < PAIRS) {
        float s, c;
        sincosf(angles[p], &s, &c);
        int a0 = pairs[2 * p];
        int a1 = pairs[2 * p + 1];
        int o0 = outp_pairs[2 * p];
        int o1 = outp_pairs[2 * p + 1];
        // yi = c*x[a0] - s*x[a1] -> out[o0]
        // yj = c*x[a1] + s*x[a0] -> out[o1]
        g_src[o0] = a0 | (a1 << 12);
        g_cs[o0]  = make_float2(c, -s);
        g_src[o1] = a1 | (a0 << 12);
        g_cs[o1]  = make_float2(c, s);
    }
}

// Dynamic smem: float4 s_tile[NODES]; s_tile[n] = rows r0..r3 at node n (64 KB).
extern __shared__ float4 s_tile[];

__global__ void __launch_bounds__(THREADS, 3)
rot_kernel(const float* __restrict__ inp, float* __restrict__ outp) {
    const int tid = threadIdx.x;
    const size_t base = (size_t)blockIdx.x * R * NODES;

    const float* r0 = inp + base;
    const float* r1 = r0 + NODES;
    const float* r2 = r1 + NODES;
    const float* r3 = r2 + NODES;

    // Stage: transpose R rows into [node][row] float4 records.
    // 4 coalesced LDG.32 + 1 sequential STS.128 (conflict-free) per node.
    // Does NOT need the map — overlaps with setup_kernel via PDL.
#pragma unroll
    for (int i = 0; i < ITERS; i++) {
        int n = tid + i * THREADS;
        float4 v;
        v.x = r0[n];
        v.y = r1[n];
        v.z = r2[n];
        v.w = r3[n];
        s_tile[n] = v;
    }

    // Wait for setup_kernel's map writes to be visible.
    cudaGridDependencySynchronize();
    __syncthreads();

    float* o0 = outp + base;
    float* o1 = o0 + NODES;
    float* o2 = o1 + NODES;
    float* o3 = o2 + NODES;

    // Rolling 1-deep map prefetch (keeps regs low for 3 CTAs/SM).
    int    msrc = g_src[tid];
    float2 mcs  = g_cs[tid];

#pragma unroll
    for (int i = 0; i < ITERS; i++) {
        int n = tid + i * THREADS;
        int    cs_src = msrc;
        float2 cs_ab  = mcs;
        if (i + 1 < ITERS) {
            msrc = g_src[n + THREADS];
            mcs  = g_cs[n + THREADS];
        }
        int s0 = cs_src & 0xFFF;
        int s1 = cs_src >> 12;
        float a = cs_ab.x;
        float b = cs_ab.y;
        float4 x = s_tile[s0];
        float4 y = s_tile[s1];
        o0[n] = a * x.x + b * y.x;
        o1[n] = a * x.y + b * y.y;
        o2[n] = a * x.z + b * y.z;
        o3[n] = a * x.w + b * y.w;
    }
}

extern "C" void kernel_launch(void* const* d_in, const int* in_sizes, int n_in,
                              void* d_out, int out_size) {
    const float* inp        = (const float*)d_in[0];
    const float* angles     = (const float*)d_in[1];
    const int*   pairs      = (const int*)d_in[2];
    const int*   outp_pairs = (const int*)d_in[3];
    float*       outp       = (float*)d_out;

    int rows = in_sizes[0] / NODES;           // 8192
    int smem = NODES * sizeof(float4);        // 64 KB

    static bool attr_set = false;
    if (!attr_set) {
        cudaFuncSetAttribute(rot_kernel,
                             cudaFuncAttributeMaxDynamicSharedMemorySize, smem);
        attr_set = true;
    }

    setup_kernel<<<PAIRS / 256, 256>>>(angles, pairs, outp_pairs);

    // Launch rot_kernel with programmatic stream serialization so its staging
    // phase overlaps setup_kernel's sincosf/scatter.
    cudaLaunchConfig_t cfg = {};
    cfg.gridDim        = dim3(rows / R, 1, 1);
    cfg.blockDim       = dim3(THREADS, 1, 1);
    cfg.dynamicSmemBytes = smem;
    cudaLaunchAttribute attr[1];
    attr[0].id = cudaLaunchAttributeProgrammaticStreamSerialization;
    attr[0].val.programmaticStreamSerializationAllowed = 1;
    cfg.attrs    = attr;
    cfg.numAttrs = 1;
    cudaLaunchKernelEx(&cfg, rot_kernel, inp, outp);
}